// round 12
// baseline (speedup 1.0000x reference)
#include <cuda_runtime.h>
#include <cuda_bf16.h>

#define N_    4096
#define FIN_  500
#define H_    64
#define C_    7
#define E_    65536
#define B_    1024
#define A_    20
#define NW_   128          // bitset words per row
#define CH_   (C_*H_)      // 448
#define HB_   65536        // 16-bit histogram bins
#define CAP_  2048
#define KSEL_ (E_/2)
#define KB_   50
#define NSTG_ (FIN_/KB_)   // 10

// ---------------- scratch (device globals; zero at module load) -------------
__device__ float    g_embed[N_*H_];
__device__ unsigned g_adj[N_*NW_];
__device__ int      g_cls[N_];
__device__ float    g_thresh;
__device__ int      g_hist[HB_];

// ---------------- packed f32x2 helpers --------------------------------------
__device__ __forceinline__ unsigned long long pack2(float lo, float hi) {
    unsigned long long v;
    asm("mov.b64 %0, {%1, %2};" : "=l"(v) : "f"(lo), "f"(hi));
    return v;
}
__device__ __forceinline__ void unpack2(unsigned long long v, float& lo, float& hi) {
    asm("mov.b64 {%0, %1}, %2;" : "=f"(lo), "=f"(hi) : "l"(v));
}
__device__ __forceinline__ void fma2(unsigned long long& d,
                                     unsigned long long a, unsigned long long b) {
    asm("fma.rn.f32x2 %0, %1, %2, %0;" : "+l"(d) : "l"(a), "l"(b));
}

// ---------------- 1a) histogram (float4) + zero g_adj -----------------------
__global__ void k_hist(const float* __restrict__ w) {
    int i = blockIdx.x * blockDim.x + threadIdx.x;     // 16384 threads
    float4 wv = ((const float4*)w)[i];
    atomicAdd(&g_hist[__float_as_uint(wv.x) >> 16], 1);
    atomicAdd(&g_hist[__float_as_uint(wv.y) >> 16], 1);
    atomicAdd(&g_hist[__float_as_uint(wv.z) >> 16], 1);
    atomicAdd(&g_hist[__float_as_uint(wv.w) >> 16], 1);
    uint4 z = make_uint4(0u, 0u, 0u, 0u);
#pragma unroll
    for (int j = 0; j < 8; j++)
        ((uint4*)g_adj)[i + j*16384] = z;              // 131072 uint4 total
}

// ---------------- 1b) exact k-th largest (vectorized scans) -----------------
__global__ void k_pick(const float* __restrict__ w, int k) {
    __shared__ int s_scan[1024];
    __shared__ unsigned s_cand[CAP_];
    __shared__ int s_n, s_bucket, s_krem;
    int tid = threadIdx.x;
    const int CHK = 64;
    int abase = HB_ - (tid + 1) * CHK;

    int psum = 0;
    const int4* hp = (const int4*)(g_hist + abase);
#pragma unroll
    for (int i = 0; i < 16; i++) {
        int4 h4 = hp[i];
        psum += h4.x + h4.y + h4.z + h4.w;
    }
    s_scan[tid] = psum;
    __syncthreads();
    for (int off = 1; off < 1024; off <<= 1) {
        int v = (tid >= off) ? s_scan[tid - off] : 0;
        __syncthreads();
        s_scan[tid] += v;
        __syncthreads();
    }
    int incl = s_scan[tid];
    int excl = incl - psum;
    if (excl < k && incl >= k) {
        int cum = excl;
        int dbase = HB_ - 1 - tid * CHK;
        for (int i = 0; i < CHK; i++) {
            int b = dbase - i;
            int h = g_hist[b];
            cum += h;
            if (cum >= k) { s_bucket = b; s_krem = k - (cum - h); break; }
        }
    }
    if (tid == 0) s_n = 0;
    __syncthreads();
    int4 z4 = make_int4(0, 0, 0, 0);
#pragma unroll
    for (int i = 0; i < 16; i++) ((int4*)(g_hist + abase))[i] = z4;

    int bucket = s_bucket;
    const uint4* wp = (const uint4*)w;
#pragma unroll 4
    for (int i = tid; i < E_/4; i += 1024) {
        uint4 k4 = wp[i];
        unsigned kk;
        kk = k4.x; if ((int)(kk >> 16) == bucket) { int p = atomicAdd(&s_n, 1); if (p < CAP_) s_cand[p] = kk; }
        kk = k4.y; if ((int)(kk >> 16) == bucket) { int p = atomicAdd(&s_n, 1); if (p < CAP_) s_cand[p] = kk; }
        kk = k4.z; if ((int)(kk >> 16) == bucket) { int p = atomicAdd(&s_n, 1); if (p < CAP_) s_cand[p] = kk; }
        kk = k4.w; if ((int)(kk >> 16) == bucket) { int p = atomicAdd(&s_n, 1); if (p < CAP_) s_cand[p] = kk; }
    }
    __syncthreads();
    int n = s_n < CAP_ ? s_n : CAP_;
    int krem = s_krem;
    for (int i = tid; i < n; i += 1024) {
        unsigned v = s_cand[i];
        int gt = 0, eq = 0;
        for (int j = 0; j < n; j++) {
            unsigned u = s_cand[j];
            gt += (u > v); eq += (u == v);
        }
        if (gt < krem && krem <= gt + eq)
            g_thresh = __uint_as_float(v);
    }
}

// ---------------- 2) encoder: 16-row x 32-col tiles, grid 512, 128 thr ------
// blockIdx: tile = bid>>1 (rows), half = bid&1 (cols 0-31 / 32-63).
// Thread = 1 row x 4 cols; 3.5 blocks/SM -> cross-block latency hiding.
__global__ __launch_bounds__(128, 4) void k_encoder(
        const float* __restrict__ x,
        const float* __restrict__ Wenc,
        const float* __restrict__ benc) {
    __shared__ __align__(16) float xs[2][16][KB_];   // [buf][row][kk]  6.4 KB
    __shared__ __align__(16) float ws[2][KB_][32];   // [buf][kk][col] 12.8 KB
    int tid = threadIdx.x;                 // 128
    int row = tid & 15;
    int colg = tid >> 4;                   // 0..7
    int half = blockIdx.x & 1;
    int r0   = (blockIdx.x >> 1) * 16;
    int c0   = colg * 4;                   // within 32-col half
    int cg0  = half * 32 + c0;             // global column

    unsigned long long acc0a = 0ull, acc0b = 0ull;
    unsigned long long acc1a = 0ull, acc1b = 0ull;
    float xr[7]; float4 wr[4];

    {   // prologue: stage 0 (x: 800 scalars / 7 rounds, w: 400 float4 / 4)
#pragma unroll
        for (int j = 0; j < 7; j++) {
            int i = tid + j*128;
            if (i < 800) xr[j] = x[(r0 + i/KB_)*FIN_ + (i % KB_)];
        }
#pragma unroll
        for (int j = 0; j < 4; j++) {
            int i = tid + j*128;
            if (i < 400) wr[j] = *(const float4*)&Wenc[(i >> 3)*H_ + half*32 + (i & 7)*4];
        }
#pragma unroll
        for (int j = 0; j < 7; j++) {
            int i = tid + j*128;
            if (i < 800) ((float*)xs[0])[i] = xr[j];
        }
#pragma unroll
        for (int j = 0; j < 4; j++) {
            int i = tid + j*128;
            if (i < 400) ((float4*)ws[0])[i] = wr[j];
        }
    }
    __syncthreads();

    for (int s = 0; s < NSTG_; s++) {
        int buf = s & 1;
        if (s + 1 < NSTG_) {
            int k0 = (s + 1) * KB_;
#pragma unroll
            for (int j = 0; j < 7; j++) {
                int i = tid + j*128;
                if (i < 800) xr[j] = x[(r0 + i/KB_)*FIN_ + k0 + (i % KB_)];
            }
#pragma unroll
            for (int j = 0; j < 4; j++) {
                int i = tid + j*128;
                if (i < 400) wr[j] = *(const float4*)&Wenc[(k0 + (i >> 3))*H_ + half*32 + (i & 7)*4];
            }
        }
#pragma unroll 5
        for (int kk2 = 0; kk2 < KB_/2; kk2++) {
            float2 ap = *(const float2*)&xs[buf][row][2*kk2];
            unsigned long long aa0 = pack2(ap.x, ap.x);
            unsigned long long aa1 = pack2(ap.y, ap.y);
            float4 b0 = *(const float4*)&ws[buf][2*kk2][c0];
            float4 b1 = *(const float4*)&ws[buf][2*kk2 + 1][c0];
            fma2(acc0a, aa0, pack2(b0.x, b0.y));
            fma2(acc1a, aa0, pack2(b0.z, b0.w));
            fma2(acc0b, aa1, pack2(b1.x, b1.y));
            fma2(acc1b, aa1, pack2(b1.z, b1.w));
        }
        if (s + 1 < NSTG_) {
            int nb = buf ^ 1;
#pragma unroll
            for (int j = 0; j < 7; j++) {
                int i = tid + j*128;
                if (i < 800) ((float*)xs[nb])[i] = xr[j];
            }
#pragma unroll
            for (int j = 0; j < 4; j++) {
                int i = tid + j*128;
                if (i < 400) ((float4*)ws[nb])[i] = wr[j];
            }
        }
        __syncthreads();
    }
    float v0a, v1a, v0b, v1b, v2a, v3a, v2b, v3b;
    unpack2(acc0a, v0a, v1a); unpack2(acc0b, v0b, v1b);
    unpack2(acc1a, v2a, v3a); unpack2(acc1b, v2b, v3b);
    float v0 = v0a + v0b + benc[cg0];
    float v1 = v1a + v1b + benc[cg0+1];
    float v2 = v2a + v2b + benc[cg0+2];
    float v3 = v3a + v3b + benc[cg0+3];
    *(float4*)&g_embed[(r0 + row)*H_ + cg0] =
        make_float4(fmaxf(v0,0.f), fmaxf(v1,0.f), fmaxf(v2,0.f), fmaxf(v3,0.f));
}

// ---------------- 3) adjacency bitset ---------------------------------------
__global__ void k_adj(const int* __restrict__ ei, const float* __restrict__ ew) {
    int i = blockIdx.x * blockDim.x + threadIdx.x;
    float th = g_thresh;
    if (i < E_) {
        if (ew[i] >= th) {
            int s = ei[i], d = ei[E_ + i];
            atomicOr(&g_adj[s*NW_ + (d >> 5)], 1u << (d & 31));
        }
    } else if (i < E_ + N_) {
        int n = i - E_;
        atomicOr(&g_adj[n*NW_ + (n >> 5)], 1u << (n & 31));   // diag
    }
}

// ---------------- 4) anchors (in-block) + class assign + log_softmax --------
__global__ void k_cls(const int* __restrict__ aidx,
                      const float* __restrict__ Wpred,
                      const float* __restrict__ bpred,
                      float* __restrict__ out) {
    __shared__ float sa[C_][64];
    __shared__ float sa2[C_];
    __shared__ float swp[64*C_];
    __shared__ float sbp[C_];
    int tid = threadIdx.x;           // 128
    if (tid < 64) {
        for (int c = 0; c < C_; c++) {
            float s = 0.f;
#pragma unroll 5
            for (int a = 0; a < A_; a++)
                s += g_embed[aidx[c*A_ + a]*64 + tid];
            sa[c][tid] = s * (1.f / A_);
        }
    } else {
        for (int i = tid - 64; i < 64*C_; i += 64) swp[i] = Wpred[i];
        if (tid - 64 < C_) sbp[tid - 64] = bpred[tid - 64];
    }
    __syncthreads();
    if (tid < C_) {
        float s = 0.f;
        for (int h = 0; h < 64; h++) { float v = sa[tid][h]; s += v*v; }
        sa2[tid] = s;
    }
    __syncthreads();

    int n = blockIdx.x * 128 + tid;
    float e[64];
    const float4* ep = (const float4*)(g_embed + n*64);
#pragma unroll
    for (int i = 0; i < 16; i++) {
        float4 v = ep[i];
        e[4*i] = v.x; e[4*i+1] = v.y; e[4*i+2] = v.z; e[4*i+3] = v.w;
    }
    float en2 = 0.f;
#pragma unroll
    for (int h = 0; h < 64; h++) en2 += e[h]*e[h];
    int best = 0; float bd = 3.4e38f;
    for (int c = 0; c < C_; c++) {
        float dot = 0.f;
#pragma unroll
        for (int h = 0; h < 64; h++) dot += e[h] * sa[c][h];
        float d2 = en2 - 2.f*dot + sa2[c];
        if (d2 < bd) { bd = d2; best = c; }
    }
    g_cls[n] = best;
    float xo[C_];
    for (int c = 0; c < C_; c++) {
        float s = sbp[c];
#pragma unroll
        for (int h = 0; h < 64; h++) s += e[h] * swp[h*C_ + c];
        xo[c] = s;
    }
    float m = xo[0];
    for (int c = 1; c < C_; c++) m = fmaxf(m, xo[c]);
    float se = 0.f;
    for (int c = 0; c < C_; c++) se += expf(xo[c] - m);
    float ls = logf(se);
    for (int c = 0; c < C_; c++) out[2*B_ + n*C_ + c] = xo[c] - m - ls;
}

// ---------------- 5) fused 2-hop + class-mean + decoder, 3 queries parallel --
#define L1CAP_ 512
#define L2CAP_ 1536
__device__ __forceinline__ void barg(int t) {
    asm volatile("bar.sync %0, 128;" :: "r"(t + 1) : "memory");
}
__global__ __launch_bounds__(384) void k_cmean_dec(
        const int* __restrict__ ego, const int* __restrict__ pos,
        const int* __restrict__ neg,
        const float* __restrict__ W1, const float* __restrict__ b1,
        const float* __restrict__ W2, const float* __restrict__ b2,
        float* __restrict__ out) {
    __shared__ unsigned hop[3][NW_];
    __shared__ int   list1[3][L1CAP_];
    __shared__ int   list[3][L2CAP_];     // node | (cls<<12)
    __shared__ float sums[3][CH_];
    __shared__ int   cnt[3][C_];
    __shared__ int   n1[3], nlist[3];
    __shared__ float op[CH_], on[CH_];
    __shared__ float part[8][32];

    int b = blockIdx.x;
    int tid = threadIdx.x;            // 384
    int t   = tid >> 7;               // query group 0..2
    int gt  = tid & 127;              // id within group
    int gw  = gt >> 5;                // warp within group 0..3
    int lane = tid & 31;

    int v = (t == 0) ? ego[b] : (t == 1) ? pos[b] : neg[b];
    for (int i = gt; i < CH_; i += 128) sums[t][i] = 0.f;
    if (gt < C_) cnt[t][gt] = 0;
    if (gt == 0) { n1[t] = 0; nlist[t] = 0; }
    hop[t][gt] = g_adj[v*NW_ + gt];
    barg(t);

    {
        unsigned bits = hop[t][gt];
        while (bits) {
            int bb = __ffs(bits) - 1; bits &= bits - 1;
            int p = atomicAdd(&n1[t], 1);
            if (p < L1CAP_) list1[t][p] = gt*32 + bb;
        }
    }
    barg(t);
    int m1 = n1[t]; if (m1 > L1CAP_) m1 = L1CAP_;

    for (int j = gw; j < m1; j += 4) {
        const uint4* rp = (const uint4*)&g_adj[list1[t][j]*NW_];
        uint4 r4 = rp[lane];
        if (r4.x) atomicOr(&hop[t][lane*4 + 0], r4.x);
        if (r4.y) atomicOr(&hop[t][lane*4 + 1], r4.y);
        if (r4.z) atomicOr(&hop[t][lane*4 + 2], r4.z);
        if (r4.w) atomicOr(&hop[t][lane*4 + 3], r4.w);
    }
    barg(t);

    {
        unsigned bits = hop[t][gt];
        while (bits) {
            int bb = __ffs(bits) - 1; bits &= bits - 1;
            int node = gt*32 + bb;
            int p = atomicAdd(&nlist[t], 1);
            if (p < L2CAP_) list[t][p] = node | (g_cls[node] << 12);
        }
    }
    barg(t);

    int M = nlist[t]; if (M > L2CAP_) M = L2CAP_;
    for (int li = gw; li < M; li += 4) {
        int e = list[t][li];
        int n = e & 0xFFF, c = e >> 12;
        float2 e2 = *(const float2*)&g_embed[n*H_ + lane*2];
        atomicAdd(&sums[t][c*H_ + lane*2],     e2.x);
        atomicAdd(&sums[t][c*H_ + lane*2 + 1], e2.y);
        if (lane == 0) atomicAdd(&cnt[t][c], 1);
    }
    __syncthreads();   // all three groups done

    for (int i = tid; i < CH_; i += 384) {
        int c = i >> 6;
        float ce = (float)max(cnt[0][c], 1);
        float cp = (float)max(cnt[1][c], 1);
        float cn = (float)max(cnt[2][c], 1);
        float e  = sums[0][i] / ce;
        float p  = sums[1][i] / cp;
        float nn = sums[2][i] / cn;
        float dp = e - p, dn = e - nn;
        op[i] = dp*dp;
        on[i] = dn*dn;
    }
    __syncthreads();

    int warp = tid >> 5;
    if (warp < 8) {
        const float* o = (warp < 4) ? op : on;
        int i0 = (warp & 3) * 112;
        float h = 0.f;
        for (int i = i0; i < i0 + 112; i++)
            h += o[i] * W1[i*32 + lane];
        part[warp][lane] = h;
    }
    __syncthreads();
    if (warp == 0 || warp == 4) {
        int pb = warp;
        float hv = part[pb][lane] + part[pb+1][lane]
                 + part[pb+2][lane] + part[pb+3][lane] + b1[lane];
        hv = fmaxf(hv, 0.f);
        float vv = hv * W2[lane];
#pragma unroll
        for (int o2 = 16; o2 > 0; o2 >>= 1)
            vv += __shfl_down_sync(0xffffffffu, vv, o2);
        if (lane == 0) out[(warp == 0) ? b : (B_ + b)] = vv + b2[0];
    }
}

// ---------------- stream fork resources (host-side, created at load) --------
struct HxStreams {
    cudaStream_t s2 = nullptr;
    cudaEvent_t  fork = nullptr, join = nullptr;
    bool ok = false;
    HxStreams() {
        if (cudaStreamCreateWithFlags(&s2, cudaStreamNonBlocking) != cudaSuccess) return;
        if (cudaEventCreateWithFlags(&fork, cudaEventDisableTiming) != cudaSuccess) return;
        if (cudaEventCreateWithFlags(&join, cudaEventDisableTiming) != cudaSuccess) return;
        ok = true;
    }
};
static HxStreams hx;

// ---------------- launch ------------------------------------------------------
extern "C" void kernel_launch(void* const* d_in, const int* in_sizes, int n_in,
                              void* d_out, int out_size) {
    const float* x    = (const float*)d_in[0];
    const int*   ei   = (const int*)  d_in[1];
    const int*   ego  = (const int*)  d_in[2];
    const int*   pos  = (const int*)  d_in[3];
    const int*   neg  = (const int*)  d_in[4];
    const float* ew   = (const float*)d_in[5];
    const int*   aidx = (const int*)  d_in[6];
    int wb = (in_sizes[7] == FIN_*H_) ? 7 : 8;
    const float* Wenc  = (const float*)d_in[wb + 0];
    const float* benc  = (const float*)d_in[wb + 1];
    const float* Wpred = (const float*)d_in[wb + 2];
    const float* bpred = (const float*)d_in[wb + 3];
    const float* W1    = (const float*)d_in[wb + 4];
    const float* b1    = (const float*)d_in[wb + 5];
    const float* W2    = (const float*)d_in[wb + 6];
    const float* b2    = (const float*)d_in[wb + 7];
    float* out = (float*)d_out;

    if (hx.ok) {
        cudaEventRecord(hx.fork, 0);
        cudaStreamWaitEvent(hx.s2, hx.fork, 0);

        k_hist <<<64, 256>>>(ew);
        k_pick <<<1, 1024>>>(ew, KSEL_);
        k_adj  <<<(E_ + N_ + 255)/256, 256>>>(ei, ew);

        k_encoder<<<(N_/16)*2, 128, 0, hx.s2>>>(x, Wenc, benc);
        k_cls    <<<N_/128, 128, 0, hx.s2>>>(aidx, Wpred, bpred, out);
        cudaEventRecord(hx.join, hx.s2);
        cudaStreamWaitEvent(0, hx.join, 0);

        k_cmean_dec<<<B_, 384>>>(ego, pos, neg, W1, b1, W2, b2, out);
    } else {
        k_hist   <<<64, 256>>>(ew);
        k_pick   <<<1, 1024>>>(ew, KSEL_);
        k_encoder<<<(N_/16)*2, 128>>>(x, Wenc, benc);
        k_adj    <<<(E_ + N_ + 255)/256, 256>>>(ei, ew);
        k_cls    <<<N_/128, 128>>>(aidx, Wpred, bpred, out);
        k_cmean_dec<<<B_, 384>>>(ego, pos, neg, W1, b1, W2, b2, out);
    }
}

// round 13
// speedup vs baseline: 1.0256x; 1.0256x over previous
#include <cuda_runtime.h>
#include <cuda_bf16.h>

#define N_    4096
#define FIN_  500
#define H_    64
#define C_    7
#define E_    65536
#define B_    1024
#define A_    20
#define NW_   128          // bitset words per row
#define CH_   (C_*H_)      // 448
#define HB_   65536        // 16-bit histogram bins
#define CAP_  2048
#define KSEL_ (E_/2)
#define KB_   50
#define NSTG_ (FIN_/KB_)   // 10

// ---------------- scratch (device globals; zero at module load) -------------
__device__ float    g_embed[N_*H_];
__device__ unsigned g_adj[N_*NW_];
__device__ int      g_cls[N_];
__device__ float    g_thresh;
__device__ int      g_hist[HB_];

// ---------------- packed f32x2 helpers --------------------------------------
__device__ __forceinline__ unsigned long long pack2(float lo, float hi) {
    unsigned long long v;
    asm("mov.b64 %0, {%1, %2};" : "=l"(v) : "f"(lo), "f"(hi));
    return v;
}
__device__ __forceinline__ void unpack2(unsigned long long v, float& lo, float& hi) {
    asm("mov.b64 {%0, %1}, %2;" : "=f"(lo), "=f"(hi) : "l"(v));
}
__device__ __forceinline__ void fma2(unsigned long long& d,
                                     unsigned long long a, unsigned long long b) {
    asm("fma.rn.f32x2 %0, %1, %2, %0;" : "+l"(d) : "l"(a), "l"(b));
}

// ---------------- 1a) histogram (float4) + zero g_adj -----------------------
__global__ void k_hist(const float* __restrict__ w) {
    int i = blockIdx.x * blockDim.x + threadIdx.x;     // 16384 threads
    float4 wv = ((const float4*)w)[i];
    atomicAdd(&g_hist[__float_as_uint(wv.x) >> 16], 1);
    atomicAdd(&g_hist[__float_as_uint(wv.y) >> 16], 1);
    atomicAdd(&g_hist[__float_as_uint(wv.z) >> 16], 1);
    atomicAdd(&g_hist[__float_as_uint(wv.w) >> 16], 1);
    uint4 z = make_uint4(0u, 0u, 0u, 0u);
#pragma unroll
    for (int j = 0; j < 8; j++)
        ((uint4*)g_adj)[i + j*16384] = z;              // 131072 uint4 total
}

// ---------------- 1b) exact k-th largest (vectorized scans) -----------------
__global__ void k_pick(const float* __restrict__ w, int k) {
    __shared__ int s_scan[1024];
    __shared__ unsigned s_cand[CAP_];
    __shared__ int s_n, s_bucket, s_krem;
    int tid = threadIdx.x;
    const int CHK = 64;
    int abase = HB_ - (tid + 1) * CHK;

    int psum = 0;
    const int4* hp = (const int4*)(g_hist + abase);
#pragma unroll
    for (int i = 0; i < 16; i++) {
        int4 h4 = hp[i];
        psum += h4.x + h4.y + h4.z + h4.w;
    }
    s_scan[tid] = psum;
    __syncthreads();
    for (int off = 1; off < 1024; off <<= 1) {
        int v = (tid >= off) ? s_scan[tid - off] : 0;
        __syncthreads();
        s_scan[tid] += v;
        __syncthreads();
    }
    int incl = s_scan[tid];
    int excl = incl - psum;
    if (excl < k && incl >= k) {
        int cum = excl;
        int dbase = HB_ - 1 - tid * CHK;
        for (int i = 0; i < CHK; i++) {
            int b = dbase - i;
            int h = g_hist[b];
            cum += h;
            if (cum >= k) { s_bucket = b; s_krem = k - (cum - h); break; }
        }
    }
    if (tid == 0) s_n = 0;
    __syncthreads();
    int4 z4 = make_int4(0, 0, 0, 0);
#pragma unroll
    for (int i = 0; i < 16; i++) ((int4*)(g_hist + abase))[i] = z4;

    int bucket = s_bucket;
    const uint4* wp = (const uint4*)w;
#pragma unroll 4
    for (int i = tid; i < E_/4; i += 1024) {
        uint4 k4 = wp[i];
        unsigned kk;
        kk = k4.x; if ((int)(kk >> 16) == bucket) { int p = atomicAdd(&s_n, 1); if (p < CAP_) s_cand[p] = kk; }
        kk = k4.y; if ((int)(kk >> 16) == bucket) { int p = atomicAdd(&s_n, 1); if (p < CAP_) s_cand[p] = kk; }
        kk = k4.z; if ((int)(kk >> 16) == bucket) { int p = atomicAdd(&s_n, 1); if (p < CAP_) s_cand[p] = kk; }
        kk = k4.w; if ((int)(kk >> 16) == bucket) { int p = atomicAdd(&s_n, 1); if (p < CAP_) s_cand[p] = kk; }
    }
    __syncthreads();
    int n = s_n < CAP_ ? s_n : CAP_;
    int krem = s_krem;
    for (int i = tid; i < n; i += 1024) {
        unsigned v = s_cand[i];
        int gt = 0, eq = 0;
        for (int j = 0; j < n; j++) {
            unsigned u = s_cand[j];
            gt += (u > v); eq += (u == v);
        }
        if (gt < krem && krem <= gt + eq)
            g_thresh = __uint_as_float(v);
    }
}

// ---------------- 2) encoder: 16x64 tiles, 4 independent FFMA2 chains -------
__global__ __launch_bounds__(256, 2) void k_encoder(
        const float* __restrict__ x,
        const float* __restrict__ Wenc,
        const float* __restrict__ benc) {
    __shared__ __align__(16) float xs[2][16][KB_];   // [buf][row][kk]
    __shared__ __align__(16) float ws[2][KB_][64];
    int tid = threadIdx.x;
    int row = tid & 15;
    int c0  = (tid >> 4) * 4;
    int r0  = blockIdx.x * 16;

    unsigned long long acc0a = 0ull, acc0b = 0ull;
    unsigned long long acc1a = 0ull, acc1b = 0ull;
    float xr[4]; float4 wr[4];

    {   // prologue: stage 0 (x: 800 scalars, w: 800 float4)
#pragma unroll
        for (int j = 0; j < 4; j++) {
            int i = tid + j*256;
            if (i < 800) {
                xr[j] = x[(r0 + i/KB_)*FIN_ + (i % KB_)];
                wr[j] = *(const float4*)&Wenc[(i >> 4)*H_ + (i & 15)*4];
            }
        }
#pragma unroll
        for (int j = 0; j < 4; j++) {
            int i = tid + j*256;
            if (i < 800) {
                xs[0][i / KB_][i % KB_] = xr[j];
                *(float4*)&ws[0][i >> 4][(i & 15)*4] = wr[j];
            }
        }
    }
    __syncthreads();

    for (int s = 0; s < NSTG_; s++) {
        int buf = s & 1;
        if (s + 1 < NSTG_) {
            int k0 = (s + 1) * KB_;
#pragma unroll
            for (int j = 0; j < 4; j++) {
                int i = tid + j*256;
                if (i < 800) {
                    xr[j] = x[(r0 + i/KB_)*FIN_ + k0 + (i % KB_)];
                    wr[j] = *(const float4*)&Wenc[(k0 + (i >> 4))*H_ + (i & 15)*4];
                }
            }
        }
#pragma unroll 5
        for (int kk2 = 0; kk2 < KB_/2; kk2++) {
            float2 ap = *(const float2*)&xs[buf][row][2*kk2];
            unsigned long long aa0 = pack2(ap.x, ap.x);
            unsigned long long aa1 = pack2(ap.y, ap.y);
            float4 b0 = *(const float4*)&ws[buf][2*kk2][c0];
            float4 b1 = *(const float4*)&ws[buf][2*kk2 + 1][c0];
            fma2(acc0a, aa0, pack2(b0.x, b0.y));
            fma2(acc1a, aa0, pack2(b0.z, b0.w));
            fma2(acc0b, aa1, pack2(b1.x, b1.y));
            fma2(acc1b, aa1, pack2(b1.z, b1.w));
        }
        if (s + 1 < NSTG_) {
            int nb = buf ^ 1;
#pragma unroll
            for (int j = 0; j < 4; j++) {
                int i = tid + j*256;
                if (i < 800) {
                    xs[nb][i / KB_][i % KB_] = xr[j];
                    *(float4*)&ws[nb][i >> 4][(i & 15)*4] = wr[j];
                }
            }
        }
        __syncthreads();
    }
    float v0a, v1a, v0b, v1b, v2a, v3a, v2b, v3b;
    unpack2(acc0a, v0a, v1a); unpack2(acc0b, v0b, v1b);
    unpack2(acc1a, v2a, v3a); unpack2(acc1b, v2b, v3b);
    float v0 = v0a + v0b + benc[c0];
    float v1 = v1a + v1b + benc[c0+1];
    float v2 = v2a + v2b + benc[c0+2];
    float v3 = v3a + v3b + benc[c0+3];
    *(float4*)&g_embed[(r0 + row)*H_ + c0] =
        make_float4(fmaxf(v0,0.f), fmaxf(v1,0.f), fmaxf(v2,0.f), fmaxf(v3,0.f));
}

// ---------------- 3) adjacency bitset ---------------------------------------
__global__ void k_adj(const int* __restrict__ ei, const float* __restrict__ ew) {
    int i = blockIdx.x * blockDim.x + threadIdx.x;
    float th = g_thresh;
    if (i < E_) {
        if (ew[i] >= th) {
            int s = ei[i], d = ei[E_ + i];
            atomicOr(&g_adj[s*NW_ + (d >> 5)], 1u << (d & 31));
        }
    } else if (i < E_ + N_) {
        int n = i - E_;
        atomicOr(&g_adj[n*NW_ + (n >> 5)], 1u << (n & 31));   // diag
    }
}

// ---------------- 4) anchors (in-block) + class assign + log_softmax --------
__global__ void k_cls(const int* __restrict__ aidx,
                      const float* __restrict__ Wpred,
                      const float* __restrict__ bpred,
                      float* __restrict__ out) {
    __shared__ float sa[C_][64];
    __shared__ float sa2[C_];
    __shared__ float swp[64*C_];
    __shared__ float sbp[C_];
    int tid = threadIdx.x;           // 128
    if (tid < 64) {
        for (int c = 0; c < C_; c++) {
            float s = 0.f;
#pragma unroll 5
            for (int a = 0; a < A_; a++)
                s += g_embed[aidx[c*A_ + a]*64 + tid];
            sa[c][tid] = s * (1.f / A_);
        }
    } else {
        for (int i = tid - 64; i < 64*C_; i += 64) swp[i] = Wpred[i];
        if (tid - 64 < C_) sbp[tid - 64] = bpred[tid - 64];
    }
    __syncthreads();
    if (tid < C_) {
        float s = 0.f;
        for (int h = 0; h < 64; h++) { float v = sa[tid][h]; s += v*v; }
        sa2[tid] = s;
    }
    __syncthreads();

    int n = blockIdx.x * 128 + tid;
    float e[64];
    const float4* ep = (const float4*)(g_embed + n*64);
#pragma unroll
    for (int i = 0; i < 16; i++) {
        float4 v = ep[i];
        e[4*i] = v.x; e[4*i+1] = v.y; e[4*i+2] = v.z; e[4*i+3] = v.w;
    }
    float en2 = 0.f;
#pragma unroll
    for (int h = 0; h < 64; h++) en2 += e[h]*e[h];
    int best = 0; float bd = 3.4e38f;
    for (int c = 0; c < C_; c++) {
        float dot = 0.f;
#pragma unroll
        for (int h = 0; h < 64; h++) dot += e[h] * sa[c][h];
        float d2 = en2 - 2.f*dot + sa2[c];
        if (d2 < bd) { bd = d2; best = c; }
    }
    g_cls[n] = best;
    float xo[C_];
    for (int c = 0; c < C_; c++) {
        float s = sbp[c];
#pragma unroll
        for (int h = 0; h < 64; h++) s += e[h] * swp[h*C_ + c];
        xo[c] = s;
    }
    float m = xo[0];
    for (int c = 1; c < C_; c++) m = fmaxf(m, xo[c]);
    float se = 0.f;
    for (int c = 0; c < C_; c++) se += expf(xo[c] - m);
    float ls = logf(se);
    for (int c = 0; c < C_; c++) out[2*B_ + n*C_ + c] = xo[c] - m - ls;
}

// ---------------- 5) fused 2-hop + class-mean + decoder, 3 queries parallel --
// Gather uses per-lane REGISTER accumulation (7 classes x 2 cols + 7 counts)
// and commits once per warp: 21 atomics/warp total vs 2 ATOMS per member.
#define L1CAP_ 512
#define L2CAP_ 1536
__device__ __forceinline__ void barg(int t) {
    asm volatile("bar.sync %0, 128;" :: "r"(t + 1) : "memory");
}
__global__ __launch_bounds__(384) void k_cmean_dec(
        const int* __restrict__ ego, const int* __restrict__ pos,
        const int* __restrict__ neg,
        const float* __restrict__ W1, const float* __restrict__ b1,
        const float* __restrict__ W2, const float* __restrict__ b2,
        float* __restrict__ out) {
    __shared__ unsigned hop[3][NW_];
    __shared__ int   list1[3][L1CAP_];
    __shared__ int   list[3][L2CAP_];     // node | (cls<<12)
    __shared__ float sums[3][CH_];
    __shared__ int   cnt[3][C_];
    __shared__ int   n1[3], nlist[3];
    __shared__ float op[CH_], on[CH_];
    __shared__ float part[8][32];

    int b = blockIdx.x;
    int tid = threadIdx.x;            // 384
    int t   = tid >> 7;               // query group 0..2
    int gt  = tid & 127;              // id within group
    int gw  = gt >> 5;                // warp within group 0..3
    int lane = tid & 31;

    int v = (t == 0) ? ego[b] : (t == 1) ? pos[b] : neg[b];
    for (int i = gt; i < CH_; i += 128) sums[t][i] = 0.f;
    if (gt < C_) cnt[t][gt] = 0;
    if (gt == 0) { n1[t] = 0; nlist[t] = 0; }
    hop[t][gt] = g_adj[v*NW_ + gt];
    barg(t);

    {
        unsigned bits = hop[t][gt];
        while (bits) {
            int bb = __ffs(bits) - 1; bits &= bits - 1;
            int p = atomicAdd(&n1[t], 1);
            if (p < L1CAP_) list1[t][p] = gt*32 + bb;
        }
    }
    barg(t);
    int m1 = n1[t]; if (m1 > L1CAP_) m1 = L1CAP_;

    for (int j = gw; j < m1; j += 4) {
        const uint4* rp = (const uint4*)&g_adj[list1[t][j]*NW_];
        uint4 r4 = rp[lane];
        if (r4.x) atomicOr(&hop[t][lane*4 + 0], r4.x);
        if (r4.y) atomicOr(&hop[t][lane*4 + 1], r4.y);
        if (r4.z) atomicOr(&hop[t][lane*4 + 2], r4.z);
        if (r4.w) atomicOr(&hop[t][lane*4 + 3], r4.w);
    }
    barg(t);

    {
        unsigned bits = hop[t][gt];
        while (bits) {
            int bb = __ffs(bits) - 1; bits &= bits - 1;
            int node = gt*32 + bb;
            int p = atomicAdd(&nlist[t], 1);
            if (p < L2CAP_) list[t][p] = node | (g_cls[node] << 12);
        }
    }
    barg(t);

    int M = nlist[t]; if (M > L2CAP_) M = L2CAP_;
    {
        float accx[C_], accy[C_];
        int ccnt[C_];
#pragma unroll
        for (int cc = 0; cc < C_; cc++) { accx[cc] = 0.f; accy[cc] = 0.f; ccnt[cc] = 0; }
        for (int li = gw; li < M; li += 4) {
            int e = list[t][li];
            int n = e & 0xFFF, c = e >> 12;
            float2 e2 = *(const float2*)&g_embed[n*H_ + lane*2];
#pragma unroll
            for (int cc = 0; cc < C_; cc++) {
                bool hit = (cc == c);
                accx[cc] += hit ? e2.x : 0.f;
                accy[cc] += hit ? e2.y : 0.f;
                ccnt[cc] += hit ? 1 : 0;
            }
        }
        // commit: 14 float atomics per warp + 7 count atomics (lane 0;
        // counts are lane-uniform since all lanes process the same members)
#pragma unroll
        for (int cc = 0; cc < C_; cc++) {
            atomicAdd(&sums[t][cc*H_ + lane*2],     accx[cc]);
            atomicAdd(&sums[t][cc*H_ + lane*2 + 1], accy[cc]);
            if (lane == 0 && ccnt[cc]) atomicAdd(&cnt[t][cc], ccnt[cc]);
        }
    }
    __syncthreads();   // all three groups done

    for (int i = tid; i < CH_; i += 384) {
        int c = i >> 6;
        float ce = (float)max(cnt[0][c], 1);
        float cp = (float)max(cnt[1][c], 1);
        float cn = (float)max(cnt[2][c], 1);
        float e  = sums[0][i] / ce;
        float p  = sums[1][i] / cp;
        float nn = sums[2][i] / cn;
        float dp = e - p, dn = e - nn;
        op[i] = dp*dp;
        on[i] = dn*dn;
    }
    __syncthreads();

    int warp = tid >> 5;
    if (warp < 8) {
        const float* o = (warp < 4) ? op : on;
        int i0 = (warp & 3) * 112;
        float h = 0.f;
        for (int i = i0; i < i0 + 112; i++)
            h += o[i] * W1[i*32 + lane];
        part[warp][lane] = h;
    }
    __syncthreads();
    if (warp == 0 || warp == 4) {
        int pb = warp;
        float hv = part[pb][lane] + part[pb+1][lane]
                 + part[pb+2][lane] + part[pb+3][lane] + b1[lane];
        hv = fmaxf(hv, 0.f);
        float vv = hv * W2[lane];
#pragma unroll
        for (int o2 = 16; o2 > 0; o2 >>= 1)
            vv += __shfl_down_sync(0xffffffffu, vv, o2);
        if (lane == 0) out[(warp == 0) ? b : (B_ + b)] = vv + b2[0];
    }
}

// ---------------- stream fork resources (host-side, created at load) --------
struct HxStreams {
    cudaStream_t s2 = nullptr;
    cudaEvent_t  fork = nullptr, join = nullptr;
    bool ok = false;
    HxStreams() {
        if (cudaStreamCreateWithFlags(&s2, cudaStreamNonBlocking) != cudaSuccess) return;
        if (cudaEventCreateWithFlags(&fork, cudaEventDisableTiming) != cudaSuccess) return;
        if (cudaEventCreateWithFlags(&join, cudaEventDisableTiming) != cudaSuccess) return;
        ok = true;
    }
};
static HxStreams hx;

// ---------------- launch ------------------------------------------------------
extern "C" void kernel_launch(void* const* d_in, const int* in_sizes, int n_in,
                              void* d_out, int out_size) {
    const float* x    = (const float*)d_in[0];
    const int*   ei   = (const int*)  d_in[1];
    const int*   ego  = (const int*)  d_in[2];
    const int*   pos  = (const int*)  d_in[3];
    const int*   neg  = (const int*)  d_in[4];
    const float* ew   = (const float*)d_in[5];
    const int*   aidx = (const int*)  d_in[6];
    int wb = (in_sizes[7] == FIN_*H_) ? 7 : 8;
    const float* Wenc  = (const float*)d_in[wb + 0];
    const float* benc  = (const float*)d_in[wb + 1];
    const float* Wpred = (const float*)d_in[wb + 2];
    const float* bpred = (const float*)d_in[wb + 3];
    const float* W1    = (const float*)d_in[wb + 4];
    const float* b1    = (const float*)d_in[wb + 5];
    const float* W2    = (const float*)d_in[wb + 6];
    const float* b2    = (const float*)d_in[wb + 7];
    float* out = (float*)d_out;

    if (hx.ok) {
        cudaEventRecord(hx.fork, 0);
        cudaStreamWaitEvent(hx.s2, hx.fork, 0);

        k_hist <<<64, 256>>>(ew);
        k_pick <<<1, 1024>>>(ew, KSEL_);
        k_adj  <<<(E_ + N_ + 255)/256, 256>>>(ei, ew);

        k_encoder<<<N_/16, 256, 0, hx.s2>>>(x, Wenc, benc);
        k_cls    <<<N_/128, 128, 0, hx.s2>>>(aidx, Wpred, bpred, out);
        cudaEventRecord(hx.join, hx.s2);
        cudaStreamWaitEvent(0, hx.join, 0);

        k_cmean_dec<<<B_, 384>>>(ego, pos, neg, W1, b1, W2, b2, out);
    } else {
        k_hist   <<<64, 256>>>(ew);
        k_pick   <<<1, 1024>>>(ew, KSEL_);
        k_encoder<<<N_/16, 256>>>(x, Wenc, benc);
        k_adj    <<<(E_ + N_ + 255)/256, 256>>>(ei, ew);
        k_cls    <<<N_/128, 128>>>(aidx, Wpred, bpred, out);
        k_cmean_dec<<<B_, 384>>>(ego, pos, neg, W1, b1, W2, b2, out);
    }
}

// round 15
// speedup vs baseline: 1.0689x; 1.0422x over previous
#include <cuda_runtime.h>
#include <cuda_bf16.h>

#define N_    4096
#define FIN_  500
#define H_    64
#define C_    7
#define E_    65536
#define B_    1024
#define A_    20
#define NW_   128          // bitset words per row
#define CH_   (C_*H_)      // 448
#define HB_   65536        // 16-bit histogram bins
#define CAP_  2048
#define KSEL_ (E_/2)
#define KB_   50
#define NSTG_ (FIN_/KB_)   // 10

// ---------------- scratch (device globals; zero at module load) -------------
__device__ float    g_embed[N_*H_];
__device__ unsigned g_adj[N_*NW_];
__device__ int      g_cls[N_];
__device__ float    g_thresh;
__device__ int      g_hist[HB_];

// ---------------- packed f32x2 helpers --------------------------------------
__device__ __forceinline__ unsigned long long pack2(float lo, float hi) {
    unsigned long long v;
    asm("mov.b64 %0, {%1, %2};" : "=l"(v) : "f"(lo), "f"(hi));
    return v;
}
__device__ __forceinline__ void unpack2(unsigned long long v, float& lo, float& hi) {
    asm("mov.b64 {%0, %1}, %2;" : "=f"(lo), "=f"(hi) : "l"(v));
}
__device__ __forceinline__ void fma2(unsigned long long& d,
                                     unsigned long long a, unsigned long long b) {
    asm("fma.rn.f32x2 %0, %1, %2, %0;" : "+l"(d) : "l"(a), "l"(b));
}

// ---------------- 1a) histogram (float4) + zero g_adj -----------------------
__global__ void k_hist(const float* __restrict__ w) {
    int i = blockIdx.x * blockDim.x + threadIdx.x;     // 16384 threads
    float4 wv = ((const float4*)w)[i];
    atomicAdd(&g_hist[__float_as_uint(wv.x) >> 16], 1);
    atomicAdd(&g_hist[__float_as_uint(wv.y) >> 16], 1);
    atomicAdd(&g_hist[__float_as_uint(wv.z) >> 16], 1);
    atomicAdd(&g_hist[__float_as_uint(wv.w) >> 16], 1);
    uint4 z = make_uint4(0u, 0u, 0u, 0u);
#pragma unroll
    for (int j = 0; j < 8; j++)
        ((uint4*)g_adj)[i + j*16384] = z;              // 131072 uint4 total
}

// ---------------- 1b) exact k-th largest (vectorized scans) -----------------
__global__ void k_pick(const float* __restrict__ w, int k) {
    __shared__ int s_scan[1024];
    __shared__ unsigned s_cand[CAP_];
    __shared__ int s_n, s_bucket, s_krem;
    int tid = threadIdx.x;
    const int CHK = 64;
    int abase = HB_ - (tid + 1) * CHK;

    int psum = 0;
    const int4* hp = (const int4*)(g_hist + abase);
#pragma unroll
    for (int i = 0; i < 16; i++) {
        int4 h4 = hp[i];
        psum += h4.x + h4.y + h4.z + h4.w;
    }
    s_scan[tid] = psum;
    __syncthreads();
    for (int off = 1; off < 1024; off <<= 1) {
        int v = (tid >= off) ? s_scan[tid - off] : 0;
        __syncthreads();
        s_scan[tid] += v;
        __syncthreads();
    }
    int incl = s_scan[tid];
    int excl = incl - psum;
    if (excl < k && incl >= k) {
        int cum = excl;
        int dbase = HB_ - 1 - tid * CHK;
        for (int i = 0; i < CHK; i++) {
            int b = dbase - i;
            int h = g_hist[b];
            cum += h;
            if (cum >= k) { s_bucket = b; s_krem = k - (cum - h); break; }
        }
    }
    if (tid == 0) s_n = 0;
    __syncthreads();
    int4 z4 = make_int4(0, 0, 0, 0);
#pragma unroll
    for (int i = 0; i < 16; i++) ((int4*)(g_hist + abase))[i] = z4;

    int bucket = s_bucket;
    const uint4* wp = (const uint4*)w;
#pragma unroll 4
    for (int i = tid; i < E_/4; i += 1024) {
        uint4 k4 = wp[i];
        unsigned kk;
        kk = k4.x; if ((int)(kk >> 16) == bucket) { int p = atomicAdd(&s_n, 1); if (p < CAP_) s_cand[p] = kk; }
        kk = k4.y; if ((int)(kk >> 16) == bucket) { int p = atomicAdd(&s_n, 1); if (p < CAP_) s_cand[p] = kk; }
        kk = k4.z; if ((int)(kk >> 16) == bucket) { int p = atomicAdd(&s_n, 1); if (p < CAP_) s_cand[p] = kk; }
        kk = k4.w; if ((int)(kk >> 16) == bucket) { int p = atomicAdd(&s_n, 1); if (p < CAP_) s_cand[p] = kk; }
    }
    __syncthreads();
    int n = s_n < CAP_ ? s_n : CAP_;
    int krem = s_krem;
    for (int i = tid; i < n; i += 1024) {
        unsigned v = s_cand[i];
        int gt = 0, eq = 0;
        for (int j = 0; j < n; j++) {
            unsigned u = s_cand[j];
            gt += (u > v); eq += (u == v);
        }
        if (gt < krem && krem <= gt + eq)
            g_thresh = __uint_as_float(v);
    }
}

// ---------------- 2) encoder: 16x64 tiles, 4 independent FFMA2 chains -------
__global__ __launch_bounds__(256, 2) void k_encoder(
        const float* __restrict__ x,
        const float* __restrict__ Wenc,
        const float* __restrict__ benc) {
    __shared__ __align__(16) float xs[2][16][KB_];   // [buf][row][kk]
    __shared__ __align__(16) float ws[2][KB_][64];
    int tid = threadIdx.x;
    int row = tid & 15;
    int c0  = (tid >> 4) * 4;
    int r0  = blockIdx.x * 16;

    unsigned long long acc0a = 0ull, acc0b = 0ull;
    unsigned long long acc1a = 0ull, acc1b = 0ull;
    float xr[4]; float4 wr[4];

    {   // prologue: stage 0 (x: 800 scalars, w: 800 float4)
#pragma unroll
        for (int j = 0; j < 4; j++) {
            int i = tid + j*256;
            if (i < 800) {
                xr[j] = x[(r0 + i/KB_)*FIN_ + (i % KB_)];
                wr[j] = *(const float4*)&Wenc[(i >> 4)*H_ + (i & 15)*4];
            }
        }
#pragma unroll
        for (int j = 0; j < 4; j++) {
            int i = tid + j*256;
            if (i < 800) {
                xs[0][i / KB_][i % KB_] = xr[j];
                *(float4*)&ws[0][i >> 4][(i & 15)*4] = wr[j];
            }
        }
    }
    __syncthreads();

    for (int s = 0; s < NSTG_; s++) {
        int buf = s & 1;
        if (s + 1 < NSTG_) {
            int k0 = (s + 1) * KB_;
#pragma unroll
            for (int j = 0; j < 4; j++) {
                int i = tid + j*256;
                if (i < 800) {
                    xr[j] = x[(r0 + i/KB_)*FIN_ + k0 + (i % KB_)];
                    wr[j] = *(const float4*)&Wenc[(k0 + (i >> 4))*H_ + (i & 15)*4];
                }
            }
        }
#pragma unroll 5
        for (int kk2 = 0; kk2 < KB_/2; kk2++) {
            float2 ap = *(const float2*)&xs[buf][row][2*kk2];
            unsigned long long aa0 = pack2(ap.x, ap.x);
            unsigned long long aa1 = pack2(ap.y, ap.y);
            float4 b0 = *(const float4*)&ws[buf][2*kk2][c0];
            float4 b1 = *(const float4*)&ws[buf][2*kk2 + 1][c0];
            fma2(acc0a, aa0, pack2(b0.x, b0.y));
            fma2(acc1a, aa0, pack2(b0.z, b0.w));
            fma2(acc0b, aa1, pack2(b1.x, b1.y));
            fma2(acc1b, aa1, pack2(b1.z, b1.w));
        }
        if (s + 1 < NSTG_) {
            int nb = buf ^ 1;
#pragma unroll
            for (int j = 0; j < 4; j++) {
                int i = tid + j*256;
                if (i < 800) {
                    xs[nb][i / KB_][i % KB_] = xr[j];
                    *(float4*)&ws[nb][i >> 4][(i & 15)*4] = wr[j];
                }
            }
        }
        __syncthreads();
    }
    float v0a, v1a, v0b, v1b, v2a, v3a, v2b, v3b;
    unpack2(acc0a, v0a, v1a); unpack2(acc0b, v0b, v1b);
    unpack2(acc1a, v2a, v3a); unpack2(acc1b, v2b, v3b);
    float v0 = v0a + v0b + benc[c0];
    float v1 = v1a + v1b + benc[c0+1];
    float v2 = v2a + v2b + benc[c0+2];
    float v3 = v3a + v3b + benc[c0+3];
    *(float4*)&g_embed[(r0 + row)*H_ + c0] =
        make_float4(fmaxf(v0,0.f), fmaxf(v1,0.f), fmaxf(v2,0.f), fmaxf(v3,0.f));
}

// ---------------- 3) adjacency bitset ---------------------------------------
__global__ void k_adj(const int* __restrict__ ei, const float* __restrict__ ew) {
    int i = blockIdx.x * blockDim.x + threadIdx.x;
    float th = g_thresh;
    if (i < E_) {
        if (ew[i] >= th) {
            int s = ei[i], d = ei[E_ + i];
            atomicOr(&g_adj[s*NW_ + (d >> 5)], 1u << (d & 31));
        }
    } else if (i < E_ + N_) {
        int n = i - E_;
        atomicOr(&g_adj[n*NW_ + (n >> 5)], 1u << (n & 31));   // diag
    }
}

// ---------------- 4a) anchors + class assignment ONLY (serial path) ---------
__global__ void k_clsa(const int* __restrict__ aidx) {
    __shared__ float sa[C_][64];
    __shared__ float sa2[C_];
    int tid = threadIdx.x;           // 128
    if (tid < 64) {
        for (int c = 0; c < C_; c++) {
            float s = 0.f;
#pragma unroll 5
            for (int a = 0; a < A_; a++)
                s += g_embed[aidx[c*A_ + a]*64 + tid];
            sa[c][tid] = s * (1.f / A_);
        }
    }
    __syncthreads();
    if (tid < C_) {
        float s = 0.f;
        for (int h = 0; h < 64; h++) { float v = sa[tid][h]; s += v*v; }
        sa2[tid] = s;
    }
    __syncthreads();

    int n = blockIdx.x * 128 + tid;
    float dot[C_];
#pragma unroll
    for (int c = 0; c < C_; c++) dot[c] = 0.f;
    float en2 = 0.f;
    const float4* ep = (const float4*)(g_embed + n*64);
#pragma unroll
    for (int i = 0; i < 16; i++) {
        float4 e4 = ep[i];
        en2 += e4.x*e4.x + e4.y*e4.y + e4.z*e4.z + e4.w*e4.w;
#pragma unroll
        for (int c = 0; c < C_; c++)
            dot[c] += e4.x*sa[c][4*i]   + e4.y*sa[c][4*i+1]
                    + e4.z*sa[c][4*i+2] + e4.w*sa[c][4*i+3];
    }
    int best = 0; float bd = 3.4e38f;
#pragma unroll
    for (int c = 0; c < C_; c++) {
        float d2 = en2 - 2.f*dot[c] + sa2[c];
        if (d2 < bd) { bd = d2; best = c; }
    }
    g_cls[n] = best;
}

// ---------------- 4b) log-softmax output (overlaps cmean_dec) ---------------
__global__ void k_soft(const float* __restrict__ Wpred,
                       const float* __restrict__ bpred,
                       float* __restrict__ out) {
    __shared__ float swp[64*C_];
    __shared__ float sbp[C_];
    int tid = threadIdx.x;           // 128
    for (int i = tid; i < 64*C_; i += 128) swp[i] = Wpred[i];
    if (tid < C_) sbp[tid] = bpred[tid];
    __syncthreads();

    int n = blockIdx.x * 128 + tid;
    float xo[C_];
#pragma unroll
    for (int c = 0; c < C_; c++) xo[c] = sbp[c];
    const float4* ep = (const float4*)(g_embed + n*64);
#pragma unroll
    for (int i = 0; i < 16; i++) {
        float4 e4 = ep[i];
#pragma unroll
        for (int c = 0; c < C_; c++)
            xo[c] += e4.x*swp[(4*i)*C_ + c]   + e4.y*swp[(4*i+1)*C_ + c]
                   + e4.z*swp[(4*i+2)*C_ + c] + e4.w*swp[(4*i+3)*C_ + c];
    }
    float m = xo[0];
#pragma unroll
    for (int c = 1; c < C_; c++) m = fmaxf(m, xo[c]);
    float se = 0.f;
#pragma unroll
    for (int c = 0; c < C_; c++) se += expf(xo[c] - m);
    float ls = logf(se);
#pragma unroll
    for (int c = 0; c < C_; c++) out[2*B_ + n*C_ + c] = xo[c] - m - ls;
}

// ---------------- 5) fused 2-hop + class-mean + decoder, 3 queries parallel --
// Gather: register accumulation + 2-way member unroll (2 LDGs in flight).
#define L1CAP_ 512
#define L2CAP_ 1536
__device__ __forceinline__ void barg(int t) {
    asm volatile("bar.sync %0, 128;" :: "r"(t + 1) : "memory");
}
__global__ __launch_bounds__(384) void k_cmean_dec(
        const int* __restrict__ ego, const int* __restrict__ pos,
        const int* __restrict__ neg,
        const float* __restrict__ W1, const float* __restrict__ b1,
        const float* __restrict__ W2, const float* __restrict__ b2,
        float* __restrict__ out) {
    __shared__ unsigned hop[3][NW_];
    __shared__ int   list1[3][L1CAP_];
    __shared__ int   list[3][L2CAP_];     // node | (cls<<12)
    __shared__ float sums[3][CH_];
    __shared__ int   cnt[3][C_];
    __shared__ int   n1[3], nlist[3];
    __shared__ float op[CH_], on[CH_];
    __shared__ float part[8][32];

    int b = blockIdx.x;
    int tid = threadIdx.x;            // 384
    int t   = tid >> 7;               // query group 0..2
    int gt  = tid & 127;              // id within group
    int gw  = gt >> 5;                // warp within group 0..3
    int lane = tid & 31;

    int v = (t == 0) ? ego[b] : (t == 1) ? pos[b] : neg[b];
    for (int i = gt; i < CH_; i += 128) sums[t][i] = 0.f;
    if (gt < C_) cnt[t][gt] = 0;
    if (gt == 0) { n1[t] = 0; nlist[t] = 0; }
    hop[t][gt] = g_adj[v*NW_ + gt];
    barg(t);

    {
        unsigned bits = hop[t][gt];
        while (bits) {
            int bb = __ffs(bits) - 1; bits &= bits - 1;
            int p = atomicAdd(&n1[t], 1);
            if (p < L1CAP_) list1[t][p] = gt*32 + bb;
        }
    }
    barg(t);
    int m1 = n1[t]; if (m1 > L1CAP_) m1 = L1CAP_;

    for (int j = gw; j < m1; j += 4) {
        const uint4* rp = (const uint4*)&g_adj[list1[t][j]*NW_];
        uint4 r4 = rp[lane];
        if (r4.x) atomicOr(&hop[t][lane*4 + 0], r4.x);
        if (r4.y) atomicOr(&hop[t][lane*4 + 1], r4.y);
        if (r4.z) atomicOr(&hop[t][lane*4 + 2], r4.z);
        if (r4.w) atomicOr(&hop[t][lane*4 + 3], r4.w);
    }
    barg(t);

    {
        unsigned bits = hop[t][gt];
        while (bits) {
            int bb = __ffs(bits) - 1; bits &= bits - 1;
            int node = gt*32 + bb;
            int p = atomicAdd(&nlist[t], 1);
            if (p < L2CAP_) list[t][p] = node | (g_cls[node] << 12);
        }
    }
    barg(t);

    int M = nlist[t]; if (M > L2CAP_) M = L2CAP_;
    {
        float accx[C_], accy[C_];
        int ccnt[C_];
#pragma unroll
        for (int cc = 0; cc < C_; cc++) { accx[cc] = 0.f; accy[cc] = 0.f; ccnt[cc] = 0; }
        int li = gw;
        // 2-way unrolled: members li and li+4 processed together (2 LDGs in flight)
        for (; li + 4 < M; li += 8) {
            int ea = list[t][li], eb = list[t][li + 4];
            int na = ea & 0xFFF, ca = ea >> 12;
            int nb2 = eb & 0xFFF, cb = eb >> 12;
            float2 a2 = *(const float2*)&g_embed[na*H_ + lane*2];
            float2 b2v = *(const float2*)&g_embed[nb2*H_ + lane*2];
#pragma unroll
            for (int cc = 0; cc < C_; cc++) {
                bool ha = (cc == ca), hb = (cc == cb);
                accx[cc] += (ha ? a2.x : 0.f) + (hb ? b2v.x : 0.f);
                accy[cc] += (ha ? a2.y : 0.f) + (hb ? b2v.y : 0.f);
                ccnt[cc] += (ha ? 1 : 0) + (hb ? 1 : 0);
            }
        }
        if (li < M) {
            int e = list[t][li];
            int n = e & 0xFFF, c = e >> 12;
            float2 e2 = *(const float2*)&g_embed[n*H_ + lane*2];
#pragma unroll
            for (int cc = 0; cc < C_; cc++) {
                bool hit = (cc == c);
                accx[cc] += hit ? e2.x : 0.f;
                accy[cc] += hit ? e2.y : 0.f;
                ccnt[cc] += hit ? 1 : 0;
            }
        }
#pragma unroll
        for (int cc = 0; cc < C_; cc++) {
            atomicAdd(&sums[t][cc*H_ + lane*2],     accx[cc]);
            atomicAdd(&sums[t][cc*H_ + lane*2 + 1], accy[cc]);
            if (lane == 0 && ccnt[cc]) atomicAdd(&cnt[t][cc], ccnt[cc]);
        }
    }
    __syncthreads();   // all three groups done

    for (int i = tid; i < CH_; i += 384) {
        int c = i >> 6;
        float ce = (float)max(cnt[0][c], 1);
        float cp = (float)max(cnt[1][c], 1);
        float cn = (float)max(cnt[2][c], 1);
        float e  = sums[0][i] / ce;
        float p  = sums[1][i] / cp;
        float nn = sums[2][i] / cn;
        float dp = e - p, dn = e - nn;
        op[i] = dp*dp;
        on[i] = dn*dn;
    }
    __syncthreads();

    int warp = tid >> 5;
    if (warp < 8) {
        const float* o = (warp < 4) ? op : on;
        int i0 = (warp & 3) * 112;
        float h = 0.f;
        for (int i = i0; i < i0 + 112; i++)
            h += o[i] * W1[i*32 + lane];
        part[warp][lane] = h;
    }
    __syncthreads();
    if (warp == 0 || warp == 4) {
        int pb = warp;
        float hv = part[pb][lane] + part[pb+1][lane]
                 + part[pb+2][lane] + part[pb+3][lane] + b1[lane];
        hv = fmaxf(hv, 0.f);
        float vv = hv * W2[lane];
#pragma unroll
        for (int o2 = 16; o2 > 0; o2 >>= 1)
            vv += __shfl_down_sync(0xffffffffu, vv, o2);
        if (lane == 0) out[(warp == 0) ? b : (B_ + b)] = vv + b2[0];
    }
}

// ---------------- stream fork resources (host-side, created at load) --------
struct HxStreams {
    cudaStream_t s2 = nullptr;
    cudaEvent_t  fork = nullptr, join = nullptr, join2 = nullptr;
    bool ok = false;
    HxStreams() {
        if (cudaStreamCreateWithFlags(&s2, cudaStreamNonBlocking) != cudaSuccess) return;
        if (cudaEventCreateWithFlags(&fork, cudaEventDisableTiming) != cudaSuccess) return;
        if (cudaEventCreateWithFlags(&join, cudaEventDisableTiming) != cudaSuccess) return;
        if (cudaEventCreateWithFlags(&join2, cudaEventDisableTiming) != cudaSuccess) return;
        ok = true;
    }
};
static HxStreams hx;

// ---------------- launch ------------------------------------------------------
extern "C" void kernel_launch(void* const* d_in, const int* in_sizes, int n_in,
                              void* d_out, int out_size) {
    const float* x    = (const float*)d_in[0];
    const int*   ei   = (const int*)  d_in[1];
    const int*   ego  = (const int*)  d_in[2];
    const int*   pos  = (const int*)  d_in[3];
    const int*   neg  = (const int*)  d_in[4];
    const float* ew   = (const float*)d_in[5];
    const int*   aidx = (const int*)  d_in[6];
    int wb = (in_sizes[7] == FIN_*H_) ? 7 : 8;
    const float* Wenc  = (const float*)d_in[wb + 0];
    const float* benc  = (const float*)d_in[wb + 1];
    const float* Wpred = (const float*)d_in[wb + 2];
    const float* bpred = (const float*)d_in[wb + 3];
    const float* W1    = (const float*)d_in[wb + 4];
    const float* b1    = (const float*)d_in[wb + 5];
    const float* W2    = (const float*)d_in[wb + 6];
    const float* b2    = (const float*)d_in[wb + 7];
    float* out = (float*)d_out;

    if (hx.ok) {
        cudaEventRecord(hx.fork, 0);
        cudaStreamWaitEvent(hx.s2, hx.fork, 0);

        // edge chain on stream 0
        k_hist <<<64, 256>>>(ew);
        k_pick <<<1, 1024>>>(ew, KSEL_);
        k_adj  <<<(E_ + N_ + 255)/256, 256>>>(ei, ew);

        // embed chain on s2: encoder -> class assign; join for cmean_dec dep
        k_encoder<<<N_/16, 256, 0, hx.s2>>>(x, Wenc, benc);
        k_clsa   <<<N_/128, 128, 0, hx.s2>>>(aidx);
        cudaEventRecord(hx.join, hx.s2);
        // log-softmax stays on s2, overlapping cmean_dec on stream 0
        k_soft   <<<N_/128, 128, 0, hx.s2>>>(Wpred, bpred, out);
        cudaEventRecord(hx.join2, hx.s2);

        cudaStreamWaitEvent(0, hx.join, 0);
        k_cmean_dec<<<B_, 384>>>(ego, pos, neg, W1, b1, W2, b2, out);
        // rejoin s2's trailing work so the capture DAG is closed
        cudaStreamWaitEvent(0, hx.join2, 0);
    } else {
        k_hist   <<<64, 256>>>(ew);
        k_pick   <<<1, 1024>>>(ew, KSEL_);
        k_encoder<<<N_/16, 256>>>(x, Wenc, benc);
        k_adj    <<<(E_ + N_ + 255)/256, 256>>>(ei, ew);
        k_clsa   <<<N_/128, 128>>>(aidx);
        k_soft   <<<N_/128, 128>>>(Wpred, bpred, out);
        k_cmean_dec<<<B_, 384>>>(ego, pos, neg, W1, b1, W2, b2, out);
    }
}

// round 16
// speedup vs baseline: 1.1249x; 1.0525x over previous
#include <cuda_runtime.h>
#include <cuda_bf16.h>

#define N_    4096
#define FIN_  500
#define H_    64
#define C_    7
#define E_    65536
#define B_    1024
#define A_    20
#define NW_   128          // bitset words per row
#define CH_   (C_*H_)      // 448
#define HB_   65536        // 16-bit histogram bins
#define CAP_  2048
#define KSEL_ (E_/2)
#define KB_   50
#define NSTG_ (FIN_/KB_)   // 10

// ---------------- scratch (device globals; zero at module load) -------------
__device__ float    g_embed[N_*H_];
__device__ unsigned g_adj[N_*NW_];
__device__ int      g_cls[N_];
__device__ float    g_thresh;
__device__ int      g_hist[HB_];

// ---------------- packed f32x2 helpers --------------------------------------
__device__ __forceinline__ unsigned long long pack2(float lo, float hi) {
    unsigned long long v;
    asm("mov.b64 %0, {%1, %2};" : "=l"(v) : "f"(lo), "f"(hi));
    return v;
}
__device__ __forceinline__ void unpack2(unsigned long long v, float& lo, float& hi) {
    asm("mov.b64 {%0, %1}, %2;" : "=f"(lo), "=f"(hi) : "l"(v));
}
__device__ __forceinline__ void fma2(unsigned long long& d,
                                     unsigned long long a, unsigned long long b) {
    asm("fma.rn.f32x2 %0, %1, %2, %0;" : "+l"(d) : "l"(a), "l"(b));
}

// ---------------- 1a) histogram (float4) + zero g_adj -----------------------
__global__ void k_hist(const float* __restrict__ w) {
    int i = blockIdx.x * blockDim.x + threadIdx.x;     // 16384 threads
    float4 wv = ((const float4*)w)[i];
    atomicAdd(&g_hist[__float_as_uint(wv.x) >> 16], 1);
    atomicAdd(&g_hist[__float_as_uint(wv.y) >> 16], 1);
    atomicAdd(&g_hist[__float_as_uint(wv.z) >> 16], 1);
    atomicAdd(&g_hist[__float_as_uint(wv.w) >> 16], 1);
    uint4 z = make_uint4(0u, 0u, 0u, 0u);
#pragma unroll
    for (int j = 0; j < 8; j++)
        ((uint4*)g_adj)[i + j*16384] = z;              // 131072 uint4 total
}

// ---------------- 1b) exact k-th largest (vectorized scans) -----------------
__global__ void k_pick(const float* __restrict__ w, int k) {
    __shared__ int s_scan[1024];
    __shared__ unsigned s_cand[CAP_];
    __shared__ int s_n, s_bucket, s_krem;
    int tid = threadIdx.x;
    const int CHK = 64;
    int abase = HB_ - (tid + 1) * CHK;

    int psum = 0;
    const int4* hp = (const int4*)(g_hist + abase);
#pragma unroll
    for (int i = 0; i < 16; i++) {
        int4 h4 = hp[i];
        psum += h4.x + h4.y + h4.z + h4.w;
    }
    s_scan[tid] = psum;
    __syncthreads();
    for (int off = 1; off < 1024; off <<= 1) {
        int v = (tid >= off) ? s_scan[tid - off] : 0;
        __syncthreads();
        s_scan[tid] += v;
        __syncthreads();
    }
    int incl = s_scan[tid];
    int excl = incl - psum;
    if (excl < k && incl >= k) {
        int cum = excl;
        int dbase = HB_ - 1 - tid * CHK;
        for (int i = 0; i < CHK; i++) {
            int b = dbase - i;
            int h = g_hist[b];
            cum += h;
            if (cum >= k) { s_bucket = b; s_krem = k - (cum - h); break; }
        }
    }
    if (tid == 0) s_n = 0;
    __syncthreads();
    int4 z4 = make_int4(0, 0, 0, 0);
#pragma unroll
    for (int i = 0; i < 16; i++) ((int4*)(g_hist + abase))[i] = z4;

    int bucket = s_bucket;
    const uint4* wp = (const uint4*)w;
#pragma unroll 4
    for (int i = tid; i < E_/4; i += 1024) {
        uint4 k4 = wp[i];
        unsigned kk;
        kk = k4.x; if ((int)(kk >> 16) == bucket) { int p = atomicAdd(&s_n, 1); if (p < CAP_) s_cand[p] = kk; }
        kk = k4.y; if ((int)(kk >> 16) == bucket) { int p = atomicAdd(&s_n, 1); if (p < CAP_) s_cand[p] = kk; }
        kk = k4.z; if ((int)(kk >> 16) == bucket) { int p = atomicAdd(&s_n, 1); if (p < CAP_) s_cand[p] = kk; }
        kk = k4.w; if ((int)(kk >> 16) == bucket) { int p = atomicAdd(&s_n, 1); if (p < CAP_) s_cand[p] = kk; }
    }
    __syncthreads();
    int n = s_n < CAP_ ? s_n : CAP_;
    int krem = s_krem;
    for (int i = tid; i < n; i += 1024) {
        unsigned v = s_cand[i];
        int gt = 0, eq = 0;
        for (int j = 0; j < n; j++) {
            unsigned u = s_cand[j];
            gt += (u > v); eq += (u == v);
        }
        if (gt < krem && krem <= gt + eq)
            g_thresh = __uint_as_float(v);
    }
}

// ---------------- 2) encoder: 16x64 tiles, 4 independent FFMA2 chains -------
__global__ __launch_bounds__(256, 2) void k_encoder(
        const float* __restrict__ x,
        const float* __restrict__ Wenc,
        const float* __restrict__ benc) {
    __shared__ __align__(16) float xs[2][16][KB_];   // [buf][row][kk]
    __shared__ __align__(16) float ws[2][KB_][64];
    int tid = threadIdx.x;
    int row = tid & 15;
    int c0  = (tid >> 4) * 4;
    int r0  = blockIdx.x * 16;

    unsigned long long acc0a = 0ull, acc0b = 0ull;
    unsigned long long acc1a = 0ull, acc1b = 0ull;
    float xr[4]; float4 wr[4];

    {   // prologue: stage 0 (x: 800 scalars, w: 800 float4)
#pragma unroll
        for (int j = 0; j < 4; j++) {
            int i = tid + j*256;
            if (i < 800) {
                xr[j] = x[(r0 + i/KB_)*FIN_ + (i % KB_)];
                wr[j] = *(const float4*)&Wenc[(i >> 4)*H_ + (i & 15)*4];
            }
        }
#pragma unroll
        for (int j = 0; j < 4; j++) {
            int i = tid + j*256;
            if (i < 800) {
                xs[0][i / KB_][i % KB_] = xr[j];
                *(float4*)&ws[0][i >> 4][(i & 15)*4] = wr[j];
            }
        }
    }
    __syncthreads();

    for (int s = 0; s < NSTG_; s++) {
        int buf = s & 1;
        if (s + 1 < NSTG_) {
            int k0 = (s + 1) * KB_;
#pragma unroll
            for (int j = 0; j < 4; j++) {
                int i = tid + j*256;
                if (i < 800) {
                    xr[j] = x[(r0 + i/KB_)*FIN_ + k0 + (i % KB_)];
                    wr[j] = *(const float4*)&Wenc[(k0 + (i >> 4))*H_ + (i & 15)*4];
                }
            }
        }
#pragma unroll 5
        for (int kk2 = 0; kk2 < KB_/2; kk2++) {
            float2 ap = *(const float2*)&xs[buf][row][2*kk2];
            unsigned long long aa0 = pack2(ap.x, ap.x);
            unsigned long long aa1 = pack2(ap.y, ap.y);
            float4 b0 = *(const float4*)&ws[buf][2*kk2][c0];
            float4 b1 = *(const float4*)&ws[buf][2*kk2 + 1][c0];
            fma2(acc0a, aa0, pack2(b0.x, b0.y));
            fma2(acc1a, aa0, pack2(b0.z, b0.w));
            fma2(acc0b, aa1, pack2(b1.x, b1.y));
            fma2(acc1b, aa1, pack2(b1.z, b1.w));
        }
        if (s + 1 < NSTG_) {
            int nb = buf ^ 1;
#pragma unroll
            for (int j = 0; j < 4; j++) {
                int i = tid + j*256;
                if (i < 800) {
                    xs[nb][i / KB_][i % KB_] = xr[j];
                    *(float4*)&ws[nb][i >> 4][(i & 15)*4] = wr[j];
                }
            }
        }
        __syncthreads();
    }
    float v0a, v1a, v0b, v1b, v2a, v3a, v2b, v3b;
    unpack2(acc0a, v0a, v1a); unpack2(acc0b, v0b, v1b);
    unpack2(acc1a, v2a, v3a); unpack2(acc1b, v2b, v3b);
    float v0 = v0a + v0b + benc[c0];
    float v1 = v1a + v1b + benc[c0+1];
    float v2 = v2a + v2b + benc[c0+2];
    float v3 = v3a + v3b + benc[c0+3];
    *(float4*)&g_embed[(r0 + row)*H_ + c0] =
        make_float4(fmaxf(v0,0.f), fmaxf(v1,0.f), fmaxf(v2,0.f), fmaxf(v3,0.f));
}

// ---------------- 3) adjacency bitset ---------------------------------------
__global__ void k_adj(const int* __restrict__ ei, const float* __restrict__ ew) {
    int i = blockIdx.x * blockDim.x + threadIdx.x;
    float th = g_thresh;
    if (i < E_) {
        if (ew[i] >= th) {
            int s = ei[i], d = ei[E_ + i];
            atomicOr(&g_adj[s*NW_ + (d >> 5)], 1u << (d & 31));
        }
    } else if (i < E_ + N_) {
        int n = i - E_;
        atomicOr(&g_adj[n*NW_ + (n >> 5)], 1u << (n & 31));   // diag
    }
}

// ---------------- 4a) anchors (2-way split) + class assignment --------------
__global__ void k_clsa(const int* __restrict__ aidx) {
    __shared__ float sap[2][C_][64];
    __shared__ float sa[C_][64];
    __shared__ float sa2[C_];
    int tid = threadIdx.x;           // 128
    {
        int h = tid & 63, half = tid >> 6;   // 2 halves of the anchor list
        const int* ap = aidx + half * (A_/2);
        for (int c = 0; c < C_; c++) {
            float s = 0.f;
#pragma unroll
            for (int a = 0; a < A_/2; a++)
                s += g_embed[ap[c*A_ + a]*64 + h];
            sap[half][c][h] = s;
        }
    }
    __syncthreads();
    if (tid < 64) {
        for (int c = 0; c < C_; c++)
            sa[c][tid] = (sap[0][c][tid] + sap[1][c][tid]) * (1.f / A_);
    }
    __syncthreads();
    if (tid < C_) {
        float s = 0.f;
        for (int h = 0; h < 64; h++) { float v = sa[tid][h]; s += v*v; }
        sa2[tid] = s;
    }
    __syncthreads();

    int n = blockIdx.x * 128 + tid;
    float dot[C_];
#pragma unroll
    for (int c = 0; c < C_; c++) dot[c] = 0.f;
    float en2 = 0.f;
    const float4* ep = (const float4*)(g_embed + n*64);
#pragma unroll
    for (int i = 0; i < 16; i++) {
        float4 e4 = ep[i];
        en2 += e4.x*e4.x + e4.y*e4.y + e4.z*e4.z + e4.w*e4.w;
#pragma unroll
        for (int c = 0; c < C_; c++)
            dot[c] += e4.x*sa[c][4*i]   + e4.y*sa[c][4*i+1]
                    + e4.z*sa[c][4*i+2] + e4.w*sa[c][4*i+3];
    }
    int best = 0; float bd = 3.4e38f;
#pragma unroll
    for (int c = 0; c < C_; c++) {
        float d2 = en2 - 2.f*dot[c] + sa2[c];
        if (d2 < bd) { bd = d2; best = c; }
    }
    g_cls[n] = best;
}

// ---------------- 4b) log-softmax output (overlaps cmean_dec) ---------------
__global__ void k_soft(const float* __restrict__ Wpred,
                       const float* __restrict__ bpred,
                       float* __restrict__ out) {
    __shared__ float swp[64*C_];
    __shared__ float sbp[C_];
    int tid = threadIdx.x;           // 128
    for (int i = tid; i < 64*C_; i += 128) swp[i] = Wpred[i];
    if (tid < C_) sbp[tid] = bpred[tid];
    __syncthreads();

    int n = blockIdx.x * 128 + tid;
    float xo[C_];
#pragma unroll
    for (int c = 0; c < C_; c++) xo[c] = sbp[c];
    const float4* ep = (const float4*)(g_embed + n*64);
#pragma unroll
    for (int i = 0; i < 16; i++) {
        float4 e4 = ep[i];
#pragma unroll
        for (int c = 0; c < C_; c++)
            xo[c] += e4.x*swp[(4*i)*C_ + c]   + e4.y*swp[(4*i+1)*C_ + c]
                   + e4.z*swp[(4*i+2)*C_ + c] + e4.w*swp[(4*i+3)*C_ + c];
    }
    float m = xo[0];
#pragma unroll
    for (int c = 1; c < C_; c++) m = fmaxf(m, xo[c]);
    float se = 0.f;
#pragma unroll
    for (int c = 0; c < C_; c++) se += expf(xo[c] - m);
    float ls = logf(se);
#pragma unroll
    for (int c = 0; c < C_; c++) out[2*B_ + n*C_ + c] = xo[c] - m - ls;
}

// ---------------- 5) fused 2-hop + class-mean + decoder, 3 queries parallel --
// OR phase: 3 prefetched uint4 loads + single atomicOr commit per warp.
// Gather: register accumulation, 4-way member unroll (4 LDGs in flight).
// op/on alias dead list1 storage (smem 35.5KB -> 32KB).
#define L1CAP_ 512
#define L2CAP_ 1536
__device__ __forceinline__ void barg(int t) {
    asm volatile("bar.sync %0, 128;" :: "r"(t + 1) : "memory");
}
__global__ __launch_bounds__(384) void k_cmean_dec(
        const int* __restrict__ ego, const int* __restrict__ pos,
        const int* __restrict__ neg,
        const float* __restrict__ W1, const float* __restrict__ b1,
        const float* __restrict__ W2, const float* __restrict__ b2,
        float* __restrict__ out) {
    __shared__ unsigned hop[3][NW_];
    __shared__ int   list1[3][L1CAP_];    // later reused as op/on
    __shared__ int   list[3][L2CAP_];     // node | (cls<<12)
    __shared__ float sums[3][CH_];
    __shared__ int   cnt[3][C_];
    __shared__ int   n1[3], nlist[3];
    __shared__ float part[8][32];

    int b = blockIdx.x;
    int tid = threadIdx.x;            // 384
    int t   = tid >> 7;               // query group 0..2
    int gt  = tid & 127;              // id within group
    int gw  = gt >> 5;                // warp within group 0..3
    int lane = tid & 31;

    int v = (t == 0) ? ego[b] : (t == 1) ? pos[b] : neg[b];
    for (int i = gt; i < CH_; i += 128) sums[t][i] = 0.f;
    if (gt < C_) cnt[t][gt] = 0;
    if (gt == 0) { n1[t] = 0; nlist[t] = 0; }
    hop[t][gt] = g_adj[v*NW_ + gt];
    barg(t);

    {
        unsigned bits = hop[t][gt];
        while (bits) {
            int bb = __ffs(bits) - 1; bits &= bits - 1;
            int p = atomicAdd(&n1[t], 1);
            if (p < L1CAP_) list1[t][p] = gt*32 + bb;
        }
    }
    barg(t);
    int m1 = n1[t]; if (m1 > L1CAP_) m1 = L1CAP_;

    {   // OR neighbor rows: prefetch 3 rows/warp, OR locally, commit once
        uint4 acc = make_uint4(0u, 0u, 0u, 0u);
        int j0 = gw, j1 = gw + 4, j2 = gw + 8;
        uint4 r0v = (j0 < m1) ? ((const uint4*)&g_adj[list1[t][j0]*NW_])[lane] : acc;
        uint4 r1v = (j1 < m1) ? ((const uint4*)&g_adj[list1[t][j1]*NW_])[lane] : acc;
        uint4 r2v = (j2 < m1) ? ((const uint4*)&g_adj[list1[t][j2]*NW_])[lane] : acc;
        acc.x = r0v.x | r1v.x | r2v.x;
        acc.y = r0v.y | r1v.y | r2v.y;
        acc.z = r0v.z | r1v.z | r2v.z;
        acc.w = r0v.w | r1v.w | r2v.w;
        for (int j = gw + 12; j < m1; j += 4) {
            uint4 r4 = ((const uint4*)&g_adj[list1[t][j]*NW_])[lane];
            acc.x |= r4.x; acc.y |= r4.y; acc.z |= r4.z; acc.w |= r4.w;
        }
        if (acc.x) atomicOr(&hop[t][lane*4 + 0], acc.x);
        if (acc.y) atomicOr(&hop[t][lane*4 + 1], acc.y);
        if (acc.z) atomicOr(&hop[t][lane*4 + 2], acc.z);
        if (acc.w) atomicOr(&hop[t][lane*4 + 3], acc.w);
    }
    barg(t);

    {
        unsigned bits = hop[t][gt];
        while (bits) {
            int bb = __ffs(bits) - 1; bits &= bits - 1;
            int node = gt*32 + bb;
            int p = atomicAdd(&nlist[t], 1);
            if (p < L2CAP_) list[t][p] = node | (g_cls[node] << 12);
        }
    }
    barg(t);

    int M = nlist[t]; if (M > L2CAP_) M = L2CAP_;
    {
        float accx[C_], accy[C_];
        int ccnt[C_];
#pragma unroll
        for (int cc = 0; cc < C_; cc++) { accx[cc] = 0.f; accy[cc] = 0.f; ccnt[cc] = 0; }
        int li = gw;
        // 4-way unrolled: members li..li+12 processed together (4 LDGs in flight)
        for (; li + 12 < M; li += 16) {
            int e0 = list[t][li],      e1 = list[t][li + 4];
            int e2 = list[t][li + 8],  e3 = list[t][li + 12];
            int n0 = e0 & 0xFFF, c0 = e0 >> 12;
            int n1v = e1 & 0xFFF, c1 = e1 >> 12;
            int n2 = e2 & 0xFFF, c2 = e2 >> 12;
            int n3 = e3 & 0xFFF, c3 = e3 >> 12;
            float2 a0 = *(const float2*)&g_embed[n0*H_ + lane*2];
            float2 a1 = *(const float2*)&g_embed[n1v*H_ + lane*2];
            float2 a2 = *(const float2*)&g_embed[n2*H_ + lane*2];
            float2 a3 = *(const float2*)&g_embed[n3*H_ + lane*2];
#pragma unroll
            for (int cc = 0; cc < C_; cc++) {
                bool h0 = (cc == c0), h1 = (cc == c1), h2 = (cc == c2), h3 = (cc == c3);
                accx[cc] += (h0 ? a0.x : 0.f) + (h1 ? a1.x : 0.f)
                          + (h2 ? a2.x : 0.f) + (h3 ? a3.x : 0.f);
                accy[cc] += (h0 ? a0.y : 0.f) + (h1 ? a1.y : 0.f)
                          + (h2 ? a2.y : 0.f) + (h3 ? a3.y : 0.f);
                ccnt[cc] += (h0 ? 1 : 0) + (h1 ? 1 : 0) + (h2 ? 1 : 0) + (h3 ? 1 : 0);
            }
        }
        for (; li < M; li += 4) {
            int e = list[t][li];
            int n = e & 0xFFF, c = e >> 12;
            float2 e2 = *(const float2*)&g_embed[n*H_ + lane*2];
#pragma unroll
            for (int cc = 0; cc < C_; cc++) {
                bool hit = (cc == c);
                accx[cc] += hit ? e2.x : 0.f;
                accy[cc] += hit ? e2.y : 0.f;
                ccnt[cc] += hit ? 1 : 0;
            }
        }
#pragma unroll
        for (int cc = 0; cc < C_; cc++) {
            atomicAdd(&sums[t][cc*H_ + lane*2],     accx[cc]);
            atomicAdd(&sums[t][cc*H_ + lane*2 + 1], accy[cc]);
            if (lane == 0 && ccnt[cc]) atomicAdd(&cnt[t][cc], ccnt[cc]);
        }
    }
    __syncthreads();   // all three groups done; list1 is dead below

    float* op = (float*)&list1[0][0];   // 448 floats <= 512 ints
    float* on = (float*)&list1[1][0];
    for (int i = tid; i < CH_; i += 384) {
        int c = i >> 6;
        float ce = (float)max(cnt[0][c], 1);
        float cp = (float)max(cnt[1][c], 1);
        float cn = (float)max(cnt[2][c], 1);
        float e  = sums[0][i] / ce;
        float p  = sums[1][i] / cp;
        float nn = sums[2][i] / cn;
        float dp = e - p, dn = e - nn;
        op[i] = dp*dp;
        on[i] = dn*dn;
    }
    __syncthreads();

    int warp = tid >> 5;
    if (warp < 8) {
        const float* o = (warp < 4) ? op : on;
        int i0 = (warp & 3) * 112;
        float h = 0.f;
        for (int i = i0; i < i0 + 112; i++)
            h += o[i] * W1[i*32 + lane];
        part[warp][lane] = h;
    }
    __syncthreads();
    if (warp == 0 || warp == 4) {
        int pb = warp;
        float hv = part[pb][lane] + part[pb+1][lane]
                 + part[pb+2][lane] + part[pb+3][lane] + b1[lane];
        hv = fmaxf(hv, 0.f);
        float vv = hv * W2[lane];
#pragma unroll
        for (int o2 = 16; o2 > 0; o2 >>= 1)
            vv += __shfl_down_sync(0xffffffffu, vv, o2);
        if (lane == 0) out[(warp == 0) ? b : (B_ + b)] = vv + b2[0];
    }
}

// ---------------- stream fork resources (host-side, created at load) --------
struct HxStreams {
    cudaStream_t s2 = nullptr;
    cudaEvent_t  fork = nullptr, join = nullptr, join2 = nullptr;
    bool ok = false;
    HxStreams() {
        if (cudaStreamCreateWithFlags(&s2, cudaStreamNonBlocking) != cudaSuccess) return;
        if (cudaEventCreateWithFlags(&fork, cudaEventDisableTiming) != cudaSuccess) return;
        if (cudaEventCreateWithFlags(&join, cudaEventDisableTiming) != cudaSuccess) return;
        if (cudaEventCreateWithFlags(&join2, cudaEventDisableTiming) != cudaSuccess) return;
        ok = true;
    }
};
static HxStreams hx;

// ---------------- launch ------------------------------------------------------
extern "C" void kernel_launch(void* const* d_in, const int* in_sizes, int n_in,
                              void* d_out, int out_size) {
    const float* x    = (const float*)d_in[0];
    const int*   ei   = (const int*)  d_in[1];
    const int*   ego  = (const int*)  d_in[2];
    const int*   pos  = (const int*)  d_in[3];
    const int*   neg  = (const int*)  d_in[4];
    const float* ew   = (const float*)d_in[5];
    const int*   aidx = (const int*)  d_in[6];
    int wb = (in_sizes[7] == FIN_*H_) ? 7 : 8;
    const float* Wenc  = (const float*)d_in[wb + 0];
    const float* benc  = (const float*)d_in[wb + 1];
    const float* Wpred = (const float*)d_in[wb + 2];
    const float* bpred = (const float*)d_in[wb + 3];
    const float* W1    = (const float*)d_in[wb + 4];
    const float* b1    = (const float*)d_in[wb + 5];
    const float* W2    = (const float*)d_in[wb + 6];
    const float* b2    = (const float*)d_in[wb + 7];
    float* out = (float*)d_out;

    if (hx.ok) {
        cudaEventRecord(hx.fork, 0);
        cudaStreamWaitEvent(hx.s2, hx.fork, 0);

        // edge chain on stream 0
        k_hist <<<64, 256>>>(ew);
        k_pick <<<1, 1024>>>(ew, KSEL_);
        k_adj  <<<(E_ + N_ + 255)/256, 256>>>(ei, ew);

        // embed chain on s2: encoder -> class assign; join for cmean_dec dep
        k_encoder<<<N_/16, 256, 0, hx.s2>>>(x, Wenc, benc);
        k_clsa   <<<N_/128, 128, 0, hx.s2>>>(aidx);
        cudaEventRecord(hx.join, hx.s2);
        // log-softmax stays on s2, overlapping cmean_dec on stream 0
        k_soft   <<<N_/128, 128, 0, hx.s2>>>(Wpred, bpred, out);
        cudaEventRecord(hx.join2, hx.s2);

        cudaStreamWaitEvent(0, hx.join, 0);
        k_cmean_dec<<<B_, 384>>>(ego, pos, neg, W1, b1, W2, b2, out);
        // rejoin s2's trailing work so the capture DAG is closed
        cudaStreamWaitEvent(0, hx.join2, 0);
    } else {
        k_hist   <<<64, 256>>>(ew);
        k_pick   <<<1, 1024>>>(ew, KSEL_);
        k_encoder<<<N_/16, 256>>>(x, Wenc, benc);
        k_adj    <<<(E_ + N_ + 255)/256, 256>>>(ei, ew);
        k_clsa   <<<N_/128, 128>>>(aidx);
        k_soft   <<<N_/128, 128>>>(Wpred, bpred, out);
        k_cmean_dec<<<B_, 384>>>(ego, pos, neg, W1, b1, W2, b2, out);
    }
}